// round 12
// baseline (speedup 1.0000x reference)
#include <cuda_runtime.h>
#include <cuda_bf16.h>
#include <math.h>
#include <stdint.h>

#define N_NODES   100000
#define N_EDGES   1600000
#define IN_FEAT   512
#define HIDDEN    64
#define N_CLASSES 40
#define N_LAYERS  6

#define SCAN_NB   98   // ceil(100000/1024)

// ---------------- device scratch ----------------
__device__ float g_lin[N_NODES * HIDDEN];
__device__ float g_h  [N_NODES * HIDDEN];
__device__ float g_jk [N_NODES * HIDDEN];
__device__ float g_dinv[N_NODES];
__device__ int   g_deg [N_NODES];
__device__ int   g_off [N_NODES + 1];
__device__ int   g_cur [N_NODES];
__device__ int   g_blk [SCAN_NB];
__device__ int   g_blkpref[SCAN_NB];
__device__ int   g_csr_src[N_EDGES];
__device__ float g_csr_w  [N_EDGES];

// ---------------- degree ----------------
__global__ void k_deg_init() {
    int i = blockIdx.x * blockDim.x + threadIdx.x;
    if (i < N_NODES) g_deg[i] = 1;   // self loop
}

__global__ void k_deg_count(const int* __restrict__ dst) {
    int e = blockIdx.x * blockDim.x + threadIdx.x;
    if (e < N_EDGES) atomicAdd(&g_deg[dst[e]], 1);
}

// ---------------- scan of (deg-1) -> CSR offsets; also computes dinv ------
__global__ void k_scan1() {
    __shared__ int sh[1024];
    int i = blockIdx.x * 1024 + threadIdx.x;
    int deg = (i < N_NODES) ? g_deg[i] : 1;
    if (i < N_NODES) g_dinv[i] = rsqrtf((float)deg);
    int v = (i < N_NODES) ? (deg - 1) : 0;
    sh[threadIdx.x] = v;
    __syncthreads();
#pragma unroll
    for (int o = 1; o < 1024; o <<= 1) {
        int t = (threadIdx.x >= o) ? sh[threadIdx.x - o] : 0;
        __syncthreads();
        sh[threadIdx.x] += t;
        __syncthreads();
    }
    if (i < N_NODES) g_off[i] = sh[threadIdx.x] - v;   // exclusive, intra-block
    if (threadIdx.x == 1023) g_blk[blockIdx.x] = sh[1023];
}

__global__ void k_scan2() {
    __shared__ int sh[SCAN_NB];
    if (threadIdx.x < SCAN_NB) sh[threadIdx.x] = g_blk[threadIdx.x];
    __syncthreads();
    if (threadIdx.x == 0) {
        int run = 0;
        for (int b = 0; b < SCAN_NB; b++) { int t = sh[b]; sh[b] = run; run += t; }
        g_off[N_NODES] = N_EDGES;
    }
    __syncthreads();
    if (threadIdx.x < SCAN_NB) g_blkpref[threadIdx.x] = sh[threadIdx.x];
}

__global__ void k_scan3() {
    int i = blockIdx.x * 1024 + threadIdx.x;
    if (i < N_NODES) {
        int o = g_off[i] + g_blkpref[blockIdx.x];
        g_off[i] = o;
        g_cur[i] = o;
    }
}

__global__ void k_fill(const int* __restrict__ src, const int* __restrict__ dst) {
    int e = blockIdx.x * blockDim.x + threadIdx.x;
    if (e < N_EDGES) {
        int s = src[e], d = dst[e];
        int p = atomicAdd(&g_cur[d], 1);
        g_csr_src[p] = s;
        g_csr_w[p]   = g_dinv[s] * g_dinv[d];
    }
}

// =========== mma.sync tf32x3 GEMM: g_lin[N,64] = A[N,K] @ W[K,64] ===========
// 64x64 block tile, 128 threads (4 warps). Warp = rows warp*16..+15 x 64 cols
// (8 m16n8k8 tiles). K in chunks of 32 = 4 k8-subchunks (kq).
// Fragments pre-packed as float4 {hi(k), hi(k+4), lo(k), lo(k+4)} so every
// fragment load is ONE LDS.128. Plane pitch 257 float4 => staging stores and
// fragment loads are both bank-group conflict-free.
// tf32x3: D += Ahi*Bhi + Alo*Bhi + Ahi*Blo.

#define PLANE 257   // float4 units per kq plane (64*4 = 256, +1 pad)

__device__ __forceinline__ void mma_tf32(float d[4],
                                         uint32_t a0, uint32_t a1, uint32_t a2, uint32_t a3,
                                         uint32_t b0, uint32_t b1) {
    asm("mma.sync.aligned.m16n8k8.row.col.f32.tf32.tf32.f32 "
        "{%0,%1,%2,%3}, {%4,%5,%6,%7}, {%8,%9}, {%0,%1,%2,%3};"
        : "+f"(d[0]), "+f"(d[1]), "+f"(d[2]), "+f"(d[3])
        : "r"(a0), "r"(a1), "r"(a2), "r"(a3), "r"(b0), "r"(b1));
}

__device__ __forceinline__ float trunc_hi(float x) {
    return __uint_as_float(__float_as_uint(x) & 0xFFFFE000u);
}

template <int K, int FROM_H>
__global__ void __launch_bounds__(128)
k_gemm_mma(const float* __restrict__ A, const float* __restrict__ W) {
    __shared__ __align__(16) float4 Ast[4 * PLANE];   // [kq][r*4 + tg]
    __shared__ __align__(16) float4 Bst[4 * PLANE];   // [kq][n*4 + tg]

    const float* __restrict__ Asrc = FROM_H ? (const float*)g_h : A;

    const int tid  = threadIdx.x;
    const int warp = tid >> 5;
    const int lane = tid & 31;
    const int g    = lane >> 2;      // group id (0..7)
    const int tg   = lane & 3;       // thread in group
    const int row0 = blockIdx.x * 64;

    float d[8][4];
#pragma unroll
    for (int t = 0; t < 8; t++)
#pragma unroll
        for (int c = 0; c < 4; c++) d[t][c] = 0.f;

    const int ar0 = warp * 16 + g;
    const int ar1 = ar0 + 8;

    for (int kc = 0; kc < K; kc += 32) {
        // ---- stage A: tasks (r 0..63, kq 0..3), 2 per thread ----
#pragma unroll
        for (int pass = 0; pass < 2; pass++) {
            int idx = tid + pass * 128;         // 0..255
            int r = idx >> 2, kq = idx & 3;
            int gr = row0 + r;
            float4 v0 = make_float4(0.f, 0.f, 0.f, 0.f);
            float4 v1 = make_float4(0.f, 0.f, 0.f, 0.f);
            if (gr < N_NODES) {
                const float* p = &Asrc[(size_t)gr * K + kc + kq * 8];
                v0 = *(const float4*)p;
                v1 = *(const float4*)(p + 4);
            }
            const float a0[4] = {v0.x, v0.y, v0.z, v0.w};
            const float a1[4] = {v1.x, v1.y, v1.z, v1.w};
            float4* out = &Ast[kq * PLANE + r * 4];
#pragma unroll
            for (int t = 0; t < 4; t++) {
                float h0 = trunc_hi(a0[t]), h1 = trunc_hi(a1[t]);
                out[t] = make_float4(h0, h1, a0[t] - h0, a1[t] - h1);
            }
        }
        // ---- stage B: tasks (n 0..63, kq 0..3), 2 per thread ----
        // idx = tid + pass*128 spans 0..255; kq = idx>>6 spans 0..3. (R11 bug:
        // an extra kq adjustment aliased planes 2,3 onto 0,1 -> garbage MMA input.)
#pragma unroll
        for (int pass = 0; pass < 2; pass++) {
            int idx = tid + pass * 128;         // 0..255
            int n = idx & 63, kq = idx >> 6;    // kq 0..3
            float w[8];
#pragma unroll
            for (int j = 0; j < 8; j++)
                w[j] = W[(size_t)(kc + kq * 8 + j) * 64 + n];
            float4* out = &Bst[kq * PLANE + n * 4];
#pragma unroll
            for (int t = 0; t < 4; t++) {
                float h0 = trunc_hi(w[t]), h1 = trunc_hi(w[t + 4]);
                out[t] = make_float4(h0, h1, w[t] - h0, w[t + 4] - h1);
            }
        }
        __syncthreads();

#pragma unroll
        for (int kq = 0; kq < 4; kq++) {
            float4 fa0 = Ast[kq * PLANE + ar0 * 4 + tg];   // {hi k, hi k+4, lo k, lo k+4} row ar0
            float4 fa1 = Ast[kq * PLANE + ar1 * 4 + tg];   // row ar1
            uint32_t ah0 = __float_as_uint(fa0.x), ah1 = __float_as_uint(fa1.x);
            uint32_t ah2 = __float_as_uint(fa0.y), ah3 = __float_as_uint(fa1.y);
            uint32_t al0 = __float_as_uint(fa0.z), al1 = __float_as_uint(fa1.z);
            uint32_t al2 = __float_as_uint(fa0.w), al3 = __float_as_uint(fa1.w);
#pragma unroll
            for (int nt = 0; nt < 8; nt++) {
                int bc = nt * 8 + g;
                float4 fb = Bst[kq * PLANE + bc * 4 + tg];
                uint32_t bh0 = __float_as_uint(fb.x), bh1 = __float_as_uint(fb.y);
                uint32_t bl0 = __float_as_uint(fb.z), bl1 = __float_as_uint(fb.w);
                mma_tf32(d[nt], ah0, ah1, ah2, ah3, bh0, bh1);   // hi*hi
                mma_tf32(d[nt], al0, al1, al2, al3, bh0, bh1);   // lo*hi
                mma_tf32(d[nt], ah0, ah1, ah2, ah3, bl0, bl1);   // hi*lo
            }
        }
        __syncthreads();
    }

    // ---- epilogue: D frag (m16n8): rows g/g+8, cols 2tg, 2tg+1 ----
    const int r0 = row0 + warp * 16 + g;
    const int r1 = r0 + 8;
#pragma unroll
    for (int nt = 0; nt < 8; nt++) {
        int col = nt * 8 + 2 * tg;
        if (r0 < N_NODES)
            *(float2*)&g_lin[(size_t)r0 * 64 + col] = make_float2(d[nt][0], d[nt][1]);
        if (r1 < N_NODES)
            *(float2*)&g_lin[(size_t)r1 * 64 + col] = make_float2(d[nt][2], d[nt][3]);
    }
}

// ---------------- fused aggregation: selfloop + CSR gather + bias/relu/jk ----
template <int FIRST, int LAST>
__global__ void k_gather(const float* __restrict__ b) {
    unsigned gw   = (blockIdx.x * blockDim.x + threadIdx.x) >> 5;
    unsigned lane = threadIdx.x & 31;
    if (gw >= N_NODES) return;

    const float2* __restrict__ lin2 = (const float2*)g_lin;
    float dn = g_dinv[gw];
    float2 self = lin2[gw * 32u + lane];
    float2 acc = make_float2(dn * dn * self.x, dn * dn * self.y);

    int j = g_off[gw], end = g_off[gw + 1];
    for (; j + 4 <= end; j += 4) {
        int   s0 = g_csr_src[j],     s1 = g_csr_src[j + 1];
        int   s2 = g_csr_src[j + 2], s3 = g_csr_src[j + 3];
        float w0 = g_csr_w[j],       w1 = g_csr_w[j + 1];
        float w2 = g_csr_w[j + 2],   w3 = g_csr_w[j + 3];
        float2 m0 = lin2[(unsigned)s0 * 32u + lane];
        float2 m1 = lin2[(unsigned)s1 * 32u + lane];
        float2 m2 = lin2[(unsigned)s2 * 32u + lane];
        float2 m3 = lin2[(unsigned)s3 * 32u + lane];
        acc.x = fmaf(w0, m0.x, fmaf(w1, m1.x, fmaf(w2, m2.x, fmaf(w3, m3.x, acc.x))));
        acc.y = fmaf(w0, m0.y, fmaf(w1, m1.y, fmaf(w2, m2.y, fmaf(w3, m3.y, acc.y))));
    }
    for (; j < end; j++) {
        int s = g_csr_src[j];
        float w = g_csr_w[j];
        float2 m = lin2[(unsigned)s * 32u + lane];
        acc.x = fmaf(w, m.x, acc.x);
        acc.y = fmaf(w, m.y, acc.y);
    }

    float vx = fmaxf(acc.x + b[lane * 2],     0.f);
    float vy = fmaxf(acc.y + b[lane * 2 + 1], 0.f);
    if (!LAST)
        ((float2*)g_h)[gw * 32u + lane] = make_float2(vx, vy);
    float2* jk2 = (float2*)g_jk;
    if (FIRST) {
        jk2[gw * 32u + lane] = make_float2(vx, vy);
    } else {
        float2 o = jk2[gw * 32u + lane];
        jk2[gw * 32u + lane] = make_float2(fmaxf(o.x, vx), fmaxf(o.y, vy));
    }
}

// ---------------- final: logits = jk @ fcW + fcb; log_softmax ----------------
// 256 threads; block processes 16 nodes (4 passes of 4) reusing Wf in smem.
__global__ void k_final(const float* __restrict__ fcW,
                        const float* __restrict__ fcb,
                        float* __restrict__ out) {
    __shared__ float Wf[HIDDEN * N_CLASSES];
    __shared__ float row[4][HIDDEN];
    __shared__ float logits[4][N_CLASSES];
    __shared__ float lse[4];

    for (int i = threadIdx.x; i < HIDDEN * N_CLASSES; i += 256)
        Wf[i] = fcW[i];

    const int g = threadIdx.x >> 6;
    const int f = threadIdx.x & 63;

    for (int pass = 0; pass < 4; pass++) {
        const int node = blockIdx.x * 16 + pass * 4 + g;
        __syncthreads();

        if (node < N_NODES)
            row[g][f] = g_jk[(size_t)node * HIDDEN + f];
        __syncthreads();

        if (node < N_NODES && f < N_CLASSES) {
            float acc = fcb[f];
#pragma unroll
            for (int h = 0; h < HIDDEN; h++)
                acc = fmaf(row[g][h], Wf[h * N_CLASSES + f], acc);
            logits[g][f] = acc;
        }
        __syncthreads();

        if (node < N_NODES && f == 0) {
            float m = -INFINITY;
#pragma unroll
            for (int c = 0; c < N_CLASSES; c++) m = fmaxf(m, logits[g][c]);
            float s = 0.f;
#pragma unroll
            for (int c = 0; c < N_CLASSES; c++) s += expf(logits[g][c] - m);
            lse[g] = m + logf(s);
        }
        __syncthreads();

        if (node < N_NODES && f < N_CLASSES)
            out[(size_t)node * N_CLASSES + f] = logits[g][f] - lse[g];
    }
}

// ---------------- launch ----------------
extern "C" void kernel_launch(void* const* d_in, const int* in_sizes, int n_in,
                              void* d_out, int out_size) {
    const float* x      = (const float*)d_in[0];
    const int*   edge   = (const int*)d_in[1];     // int64 lowered to int32
    const float* W0     = (const float*)d_in[2];
    const float* b0     = (const float*)d_in[3];
    const float* W_rest = (const float*)d_in[4];
    const float* b_rest = (const float*)d_in[5];
    const float* fcW    = (const float*)d_in[6];
    const float* fcb    = (const float*)d_in[7];
    float* out = (float*)d_out;

    const int* src = edge;
    const int* dst = edge + N_EDGES;

    const int EB = (N_EDGES + 255) / 256;          // 6250
    const int NB = (N_NODES + 255) / 256;
    const int GB = (N_NODES + 63) / 64;            // 1563
    const int AB = (N_NODES * 32 + 255) / 256;     // 12500 (warp per node)

    // launch index 3 gets profiled by ncu -> big GEMM stays there.
    k_deg_init <<<NB, 256>>>();                         // 0
    k_deg_count<<<EB, 256>>>(dst);                      // 1
    k_scan1    <<<SCAN_NB, 1024>>>();                   // 2 (also dinv)
    k_gemm_mma<IN_FEAT, 0><<<GB, 128>>>(x, W0);         // 3  <- profiled
    k_scan2    <<<1, 128>>>();                          // 4
    k_scan3    <<<SCAN_NB, 1024>>>();                   // 5
    k_fill     <<<EB, 256>>>(src, dst);                 // 6

    // layer 0 aggregation
    k_gather<1, 0><<<AB, 256>>>(b0);

    // layers 1..5
    for (int l = 0; l < N_LAYERS - 1; l++) {
        k_gemm_mma<HIDDEN, 1><<<GB, 128>>>(nullptr, W_rest + (size_t)l * HIDDEN * HIDDEN);
        if (l < N_LAYERS - 2)
            k_gather<0, 0><<<AB, 256>>>(b_rest + (size_t)l * HIDDEN);
        else
            k_gather<0, 1><<<AB, 256>>>(b_rest + (size_t)l * HIDDEN);
    }

    // final FC + log_softmax
    k_final<<<(N_NODES + 15) / 16, 256>>>(fcW, fcb, out);
}

// round 13
// speedup vs baseline: 1.1295x; 1.1295x over previous
#include <cuda_runtime.h>
#include <cuda_bf16.h>
#include <math.h>
#include <stdint.h>

#define N_NODES   100000
#define N_EDGES   1600000
#define IN_FEAT   512
#define HIDDEN    64
#define N_CLASSES 40
#define N_LAYERS  6

#define SCAN_NB   98   // ceil(100000/1024)

// ---------------- device scratch ----------------
__device__ float g_lin[N_NODES * HIDDEN];
__device__ float g_h  [N_NODES * HIDDEN];
__device__ float g_jk [N_NODES * HIDDEN];
__device__ float g_dinv[N_NODES];
__device__ int   g_deg [N_NODES];
__device__ int   g_off [N_NODES + 1];
__device__ int   g_cur [N_NODES];
__device__ int   g_blk [SCAN_NB];
__device__ int   g_blkpref[SCAN_NB];
__device__ int   g_csr_src[N_EDGES];
__device__ float g_csr_w  [N_EDGES];

// ---------------- degree ----------------
__global__ void k_deg_init() {
    int i = blockIdx.x * blockDim.x + threadIdx.x;
    if (i < N_NODES) g_deg[i] = 1;   // self loop
}

__global__ void k_deg_count(const int* __restrict__ dst) {
    int e = blockIdx.x * blockDim.x + threadIdx.x;
    if (e < N_EDGES) atomicAdd(&g_deg[dst[e]], 1);
}

// ---------------- scan of (deg-1) -> CSR offsets; also computes dinv ------
__global__ void k_scan1() {
    __shared__ int sh[1024];
    int i = blockIdx.x * 1024 + threadIdx.x;
    int deg = (i < N_NODES) ? g_deg[i] : 1;
    if (i < N_NODES) g_dinv[i] = rsqrtf((float)deg);
    int v = (i < N_NODES) ? (deg - 1) : 0;
    sh[threadIdx.x] = v;
    __syncthreads();
#pragma unroll
    for (int o = 1; o < 1024; o <<= 1) {
        int t = (threadIdx.x >= o) ? sh[threadIdx.x - o] : 0;
        __syncthreads();
        sh[threadIdx.x] += t;
        __syncthreads();
    }
    if (i < N_NODES) g_off[i] = sh[threadIdx.x] - v;   // exclusive, intra-block
    if (threadIdx.x == 1023) g_blk[blockIdx.x] = sh[1023];
}

__global__ void k_scan2() {
    __shared__ int sh[SCAN_NB];
    if (threadIdx.x < SCAN_NB) sh[threadIdx.x] = g_blk[threadIdx.x];
    __syncthreads();
    if (threadIdx.x == 0) {
        int run = 0;
        for (int b = 0; b < SCAN_NB; b++) { int t = sh[b]; sh[b] = run; run += t; }
        g_off[N_NODES] = N_EDGES;
    }
    __syncthreads();
    if (threadIdx.x < SCAN_NB) g_blkpref[threadIdx.x] = sh[threadIdx.x];
}

__global__ void k_scan3() {
    int i = blockIdx.x * 1024 + threadIdx.x;
    if (i < N_NODES) {
        int o = g_off[i] + g_blkpref[blockIdx.x];
        g_off[i] = o;
        g_cur[i] = o;
    }
}

__global__ void k_fill(const int* __restrict__ src, const int* __restrict__ dst) {
    int e = blockIdx.x * blockDim.x + threadIdx.x;
    if (e < N_EDGES) {
        int s = src[e], d = dst[e];
        int p = atomicAdd(&g_cur[d], 1);
        g_csr_src[p] = s;
        g_csr_w[p]   = g_dinv[s] * g_dinv[d];
    }
}

// =========== mma.sync tf32x3 GEMM: g_lin[N,64] = A[N,K] @ W[K,64] ===========
// 64x64 block tile, 128 threads (4 warps). Warp = rows warp*16..+15 x 64 cols
// (8 m16n8k8 tiles). K in chunks of 32 = 4 k8-subchunks.
// Smem holds RAW fp32 (A pitch 36, B pitch 72 — R10's proven conflict-free
// layouts). hi/lo derived IN-REGISTER (LOP3 + FADD) after one scalar LDS per
// element: 20 LDS per warp-k8 instead of 40 (smem wavefronts are bytes-bound).
// tf32x3: D += Ahi*Bhi + Alo*Bhi + Ahi*Blo.

__device__ __forceinline__ void mma_tf32(float d[4],
                                         uint32_t a0, uint32_t a1, uint32_t a2, uint32_t a3,
                                         uint32_t b0, uint32_t b1) {
    asm("mma.sync.aligned.m16n8k8.row.col.f32.tf32.tf32.f32 "
        "{%0,%1,%2,%3}, {%4,%5,%6,%7}, {%8,%9}, {%0,%1,%2,%3};"
        : "+f"(d[0]), "+f"(d[1]), "+f"(d[2]), "+f"(d[3])
        : "r"(a0), "r"(a1), "r"(a2), "r"(a3), "r"(b0), "r"(b1));
}

__device__ __forceinline__ float trunc_hi(float x) {
    return __uint_as_float(__float_as_uint(x) & 0xFFFFE000u);
}

template <int K, int FROM_H>
__global__ void __launch_bounds__(128)
k_gemm_mma(const float* __restrict__ A, const float* __restrict__ W) {
    __shared__ __align__(16) float As[64][36];   // [row][k] raw fp32
    __shared__ __align__(16) float Bs[32][72];   // [k][n]   raw fp32

    const float* __restrict__ Asrc = FROM_H ? (const float*)g_h : A;

    const int tid  = threadIdx.x;
    const int warp = tid >> 5;
    const int lane = tid & 31;
    const int g    = lane >> 2;      // group id (0..7)
    const int tg   = lane & 3;       // thread in group
    const int row0 = blockIdx.x * 64;

    float d[8][4];
#pragma unroll
    for (int t = 0; t < 8; t++)
#pragma unroll
        for (int c = 0; c < 4; c++) d[t][c] = 0.f;

    const int ar0 = warp * 16 + g;
    const int ar1 = ar0 + 8;

    for (int kc = 0; kc < K; kc += 32) {
        // ---- stage A chunk raw: 64 rows x 32 k, float4; STS group (r+q)%8 ✓ ----
#pragma unroll
        for (int i = 0; i < 4; i++) {
            int idx = tid + i * 128;            // 0..511
            int r = idx >> 3, q = idx & 7;
            int gr = row0 + r;
            float4 v = make_float4(0.f, 0.f, 0.f, 0.f);
            if (gr < N_NODES)
                v = *(const float4*)&Asrc[(size_t)gr * K + kc + q * 4];
            *(float4*)&As[r][q * 4] = v;
        }
        // ---- stage B chunk raw: straight float4 copy of W[k][n]; group (2k+n4)%8 ✓ ----
#pragma unroll
        for (int i = 0; i < 4; i++) {
            int idx = tid + i * 128;            // 0..511
            int k = idx >> 4, n4 = idx & 15;
            *(float4*)&Bs[k][n4 * 4] =
                *(const float4*)&W[(size_t)(kc + k) * 64 + n4 * 4];
        }
        __syncthreads();

#pragma unroll
        for (int k8 = 0; k8 < 32; k8 += 8) {
            // A fragment: 4 scalar LDS, split in-register
            float a0 = As[ar0][k8 + tg];
            float a1 = As[ar1][k8 + tg];
            float a2 = As[ar0][k8 + tg + 4];
            float a3 = As[ar1][k8 + tg + 4];
            float t0 = trunc_hi(a0), t1 = trunc_hi(a1);
            float t2 = trunc_hi(a2), t3 = trunc_hi(a3);
            uint32_t ah0 = __float_as_uint(t0), ah1 = __float_as_uint(t1);
            uint32_t ah2 = __float_as_uint(t2), ah3 = __float_as_uint(t3);
            uint32_t al0 = __float_as_uint(a0 - t0), al1 = __float_as_uint(a1 - t1);
            uint32_t al2 = __float_as_uint(a2 - t2), al3 = __float_as_uint(a3 - t3);
#pragma unroll
            for (int nt = 0; nt < 8; nt++) {
                int bc = nt * 8 + g;
                float b0 = Bs[k8 + tg][bc];
                float b1 = Bs[k8 + tg + 4][bc];
                float u0 = trunc_hi(b0), u1 = trunc_hi(b1);
                uint32_t bh0 = __float_as_uint(u0), bh1 = __float_as_uint(u1);
                uint32_t bl0 = __float_as_uint(b0 - u0), bl1 = __float_as_uint(b1 - u1);
                mma_tf32(d[nt], ah0, ah1, ah2, ah3, bh0, bh1);   // hi*hi
                mma_tf32(d[nt], al0, al1, al2, al3, bh0, bh1);   // lo*hi
                mma_tf32(d[nt], ah0, ah1, ah2, ah3, bl0, bl1);   // hi*lo
            }
        }
        __syncthreads();
    }

    // ---- epilogue: D frag (m16n8): rows g/g+8, cols 2tg, 2tg+1 ----
    const int r0 = row0 + warp * 16 + g;
    const int r1 = r0 + 8;
#pragma unroll
    for (int nt = 0; nt < 8; nt++) {
        int col = nt * 8 + 2 * tg;
        if (r0 < N_NODES)
            *(float2*)&g_lin[(size_t)r0 * 64 + col] = make_float2(d[nt][0], d[nt][1]);
        if (r1 < N_NODES)
            *(float2*)&g_lin[(size_t)r1 * 64 + col] = make_float2(d[nt][2], d[nt][3]);
    }
}

// ---------------- fused aggregation: selfloop + CSR gather + bias/relu/jk ----
template <int FIRST, int LAST>
__global__ void k_gather(const float* __restrict__ b) {
    unsigned gw   = (blockIdx.x * blockDim.x + threadIdx.x) >> 5;
    unsigned lane = threadIdx.x & 31;
    if (gw >= N_NODES) return;

    const float2* __restrict__ lin2 = (const float2*)g_lin;
    float dn = g_dinv[gw];
    float2 self = lin2[gw * 32u + lane];
    float2 acc = make_float2(dn * dn * self.x, dn * dn * self.y);

    int j = g_off[gw], end = g_off[gw + 1];
    for (; j + 4 <= end; j += 4) {
        int   s0 = g_csr_src[j],     s1 = g_csr_src[j + 1];
        int   s2 = g_csr_src[j + 2], s3 = g_csr_src[j + 3];
        float w0 = g_csr_w[j],       w1 = g_csr_w[j + 1];
        float w2 = g_csr_w[j + 2],   w3 = g_csr_w[j + 3];
        float2 m0 = lin2[(unsigned)s0 * 32u + lane];
        float2 m1 = lin2[(unsigned)s1 * 32u + lane];
        float2 m2 = lin2[(unsigned)s2 * 32u + lane];
        float2 m3 = lin2[(unsigned)s3 * 32u + lane];
        acc.x = fmaf(w0, m0.x, fmaf(w1, m1.x, fmaf(w2, m2.x, fmaf(w3, m3.x, acc.x))));
        acc.y = fmaf(w0, m0.y, fmaf(w1, m1.y, fmaf(w2, m2.y, fmaf(w3, m3.y, acc.y))));
    }
    for (; j < end; j++) {
        int s = g_csr_src[j];
        float w = g_csr_w[j];
        float2 m = lin2[(unsigned)s * 32u + lane];
        acc.x = fmaf(w, m.x, acc.x);
        acc.y = fmaf(w, m.y, acc.y);
    }

    float vx = fmaxf(acc.x + b[lane * 2],     0.f);
    float vy = fmaxf(acc.y + b[lane * 2 + 1], 0.f);
    if (!LAST)
        ((float2*)g_h)[gw * 32u + lane] = make_float2(vx, vy);
    float2* jk2 = (float2*)g_jk;
    if (FIRST) {
        jk2[gw * 32u + lane] = make_float2(vx, vy);
    } else {
        float2 o = jk2[gw * 32u + lane];
        jk2[gw * 32u + lane] = make_float2(fmaxf(o.x, vx), fmaxf(o.y, vy));
    }
}

// ---------------- final: logits = jk @ fcW + fcb; log_softmax ----------------
// 256 threads; block processes 16 nodes (4 passes of 4) reusing Wf in smem.
__global__ void k_final(const float* __restrict__ fcW,
                        const float* __restrict__ fcb,
                        float* __restrict__ out) {
    __shared__ float Wf[HIDDEN * N_CLASSES];
    __shared__ float row[4][HIDDEN];
    __shared__ float logits[4][N_CLASSES];
    __shared__ float lse[4];

    for (int i = threadIdx.x; i < HIDDEN * N_CLASSES; i += 256)
        Wf[i] = fcW[i];

    const int g = threadIdx.x >> 6;
    const int f = threadIdx.x & 63;

    for (int pass = 0; pass < 4; pass++) {
        const int node = blockIdx.x * 16 + pass * 4 + g;
        __syncthreads();

        if (node < N_NODES)
            row[g][f] = g_jk[(size_t)node * HIDDEN + f];
        __syncthreads();

        if (node < N_NODES && f < N_CLASSES) {
            float acc = fcb[f];
#pragma unroll
            for (int h = 0; h < HIDDEN; h++)
                acc = fmaf(row[g][h], Wf[h * N_CLASSES + f], acc);
            logits[g][f] = acc;
        }
        __syncthreads();

        if (node < N_NODES && f == 0) {
            float m = -INFINITY;
#pragma unroll
            for (int c = 0; c < N_CLASSES; c++) m = fmaxf(m, logits[g][c]);
            float s = 0.f;
#pragma unroll
            for (int c = 0; c < N_CLASSES; c++) s += expf(logits[g][c] - m);
            lse[g] = m + logf(s);
        }
        __syncthreads();

        if (node < N_NODES && f < N_CLASSES)
            out[(size_t)node * N_CLASSES + f] = logits[g][f] - lse[g];
    }
}

// ---------------- launch ----------------
extern "C" void kernel_launch(void* const* d_in, const int* in_sizes, int n_in,
                              void* d_out, int out_size) {
    const float* x      = (const float*)d_in[0];
    const int*   edge   = (const int*)d_in[1];     // int64 lowered to int32
    const float* W0     = (const float*)d_in[2];
    const float* b0     = (const float*)d_in[3];
    const float* W_rest = (const float*)d_in[4];
    const float* b_rest = (const float*)d_in[5];
    const float* fcW    = (const float*)d_in[6];
    const float* fcb    = (const float*)d_in[7];
    float* out = (float*)d_out;

    const int* src = edge;
    const int* dst = edge + N_EDGES;

    const int EB = (N_EDGES + 255) / 256;          // 6250
    const int NB = (N_NODES + 255) / 256;
    const int GB = (N_NODES + 63) / 64;            // 1563
    const int AB = (N_NODES * 32 + 255) / 256;     // 12500 (warp per node)

    // launch index 3 gets profiled by ncu -> big GEMM stays there.
    k_deg_init <<<NB, 256>>>();                         // 0
    k_deg_count<<<EB, 256>>>(dst);                      // 1
    k_scan1    <<<SCAN_NB, 1024>>>();                   // 2 (also dinv)
    k_gemm_mma<IN_FEAT, 0><<<GB, 128>>>(x, W0);         // 3  <- profiled
    k_scan2    <<<1, 128>>>();                          // 4
    k_scan3    <<<SCAN_NB, 1024>>>();                   // 5
    k_fill     <<<EB, 256>>>(src, dst);                 // 6

    // layer 0 aggregation
    k_gather<1, 0><<<AB, 256>>>(b0);

    // layers 1..5
    for (int l = 0; l < N_LAYERS - 1; l++) {
        k_gemm_mma<HIDDEN, 1><<<GB, 128>>>(nullptr, W_rest + (size_t)l * HIDDEN * HIDDEN);
        if (l < N_LAYERS - 2)
            k_gather<0, 0><<<AB, 256>>>(b_rest + (size_t)l * HIDDEN);
        else
            k_gather<0, 1><<<AB, 256>>>(b_rest + (size_t)l * HIDDEN);
    }

    // final FC + log_softmax
    k_final<<<(N_NODES + 15) / 16, 256>>>(fcW, fcb, out);
}

// round 14
// speedup vs baseline: 1.1329x; 1.0030x over previous
#include <cuda_runtime.h>
#include <cuda_bf16.h>
#include <math.h>
#include <stdint.h>

#define N_NODES   100000
#define N_EDGES   1600000
#define IN_FEAT   512
#define HIDDEN    64
#define N_CLASSES 40
#define N_LAYERS  6

#define SCAN_NB   98   // ceil(100000/1024)

// ---------------- device scratch ----------------
__device__ float g_lin[N_NODES * HIDDEN];
__device__ float g_h  [N_NODES * HIDDEN];
__device__ float g_jk [N_NODES * HIDDEN];
__device__ float g_dinv[N_NODES];
__device__ int   g_deg [N_NODES];
__device__ int   g_off [N_NODES + 1];
__device__ int   g_cur [N_NODES];
__device__ int   g_blk [SCAN_NB];
__device__ int   g_blkpref[SCAN_NB];
__device__ int   g_csr_src[N_EDGES];
__device__ float g_csr_w  [N_EDGES];

// ---------------- degree ----------------
__global__ void k_deg_init() {
    int i = blockIdx.x * blockDim.x + threadIdx.x;
    if (i < N_NODES) g_deg[i] = 1;   // self loop
}

__global__ void k_deg_count(const int* __restrict__ dst) {
    int e = blockIdx.x * blockDim.x + threadIdx.x;
    if (e < N_EDGES) atomicAdd(&g_deg[dst[e]], 1);
}

// ---------------- scan of (deg-1) -> CSR offsets; also computes dinv ------
__global__ void k_scan1() {
    __shared__ int sh[1024];
    int i = blockIdx.x * 1024 + threadIdx.x;
    int deg = (i < N_NODES) ? g_deg[i] : 1;
    if (i < N_NODES) g_dinv[i] = rsqrtf((float)deg);
    int v = (i < N_NODES) ? (deg - 1) : 0;
    sh[threadIdx.x] = v;
    __syncthreads();
#pragma unroll
    for (int o = 1; o < 1024; o <<= 1) {
        int t = (threadIdx.x >= o) ? sh[threadIdx.x - o] : 0;
        __syncthreads();
        sh[threadIdx.x] += t;
        __syncthreads();
    }
    if (i < N_NODES) g_off[i] = sh[threadIdx.x] - v;   // exclusive, intra-block
    if (threadIdx.x == 1023) g_blk[blockIdx.x] = sh[1023];
}

__global__ void k_scan2() {
    __shared__ int sh[SCAN_NB];
    if (threadIdx.x < SCAN_NB) sh[threadIdx.x] = g_blk[threadIdx.x];
    __syncthreads();
    if (threadIdx.x == 0) {
        int run = 0;
        for (int b = 0; b < SCAN_NB; b++) { int t = sh[b]; sh[b] = run; run += t; }
        g_off[N_NODES] = N_EDGES;
    }
    __syncthreads();
    if (threadIdx.x < SCAN_NB) g_blkpref[threadIdx.x] = sh[threadIdx.x];
}

__global__ void k_scan3() {
    int i = blockIdx.x * 1024 + threadIdx.x;
    if (i < N_NODES) {
        int o = g_off[i] + g_blkpref[blockIdx.x];
        g_off[i] = o;
        g_cur[i] = o;
    }
}

__global__ void k_fill(const int* __restrict__ src, const int* __restrict__ dst) {
    int e = blockIdx.x * blockDim.x + threadIdx.x;
    if (e < N_EDGES) {
        int s = src[e], d = dst[e];
        int p = atomicAdd(&g_cur[d], 1);
        g_csr_src[p] = s;
        g_csr_w[p]   = g_dinv[s] * g_dinv[d];
    }
}

// =========== mma.sync tf32x3 GEMM: g_lin[N,64] = A[N,K] @ W[K,64] ===========
// 64x64 block tile, 128 threads (4 warps). Warp = rows warp*16..+15 x 64 cols
// (8 m16n8k8 tiles). K in chunks of 32 = 4 k8-subchunks.
// Smem raw fp32 (A pitch 36, B pitch 72 — conflict-free); hi/lo split
// in-register. Inner loop runs THREE PASSES over the 8 nt-tiles (all hi*hi,
// then all lo*hi, then all hi*lo) so consecutive MMAs never chain on the
// same accumulator (RAW distance 8 instead of 1).
// tf32x3: D += Ahi*Bhi + Alo*Bhi + Ahi*Blo.

__device__ __forceinline__ void mma_tf32(float d[4],
                                         uint32_t a0, uint32_t a1, uint32_t a2, uint32_t a3,
                                         uint32_t b0, uint32_t b1) {
    asm("mma.sync.aligned.m16n8k8.row.col.f32.tf32.tf32.f32 "
        "{%0,%1,%2,%3}, {%4,%5,%6,%7}, {%8,%9}, {%0,%1,%2,%3};"
        : "+f"(d[0]), "+f"(d[1]), "+f"(d[2]), "+f"(d[3])
        : "r"(a0), "r"(a1), "r"(a2), "r"(a3), "r"(b0), "r"(b1));
}

__device__ __forceinline__ float trunc_hi(float x) {
    return __uint_as_float(__float_as_uint(x) & 0xFFFFE000u);
}

template <int K, int FROM_H>
__global__ void __launch_bounds__(128)
k_gemm_mma(const float* __restrict__ A, const float* __restrict__ W) {
    __shared__ __align__(16) float As[64][36];   // [row][k] raw fp32
    __shared__ __align__(16) float Bs[32][72];   // [k][n]   raw fp32

    const float* __restrict__ Asrc = FROM_H ? (const float*)g_h : A;

    const int tid  = threadIdx.x;
    const int warp = tid >> 5;
    const int lane = tid & 31;
    const int g    = lane >> 2;      // group id (0..7)
    const int tg   = lane & 3;       // thread in group
    const int row0 = blockIdx.x * 64;

    float d[8][4];
#pragma unroll
    for (int t = 0; t < 8; t++)
#pragma unroll
        for (int c = 0; c < 4; c++) d[t][c] = 0.f;

    const int ar0 = warp * 16 + g;
    const int ar1 = ar0 + 8;

    for (int kc = 0; kc < K; kc += 32) {
        // ---- stage A chunk raw: 64 rows x 32 k, float4 ----
#pragma unroll
        for (int i = 0; i < 4; i++) {
            int idx = tid + i * 128;            // 0..511
            int r = idx >> 3, q = idx & 7;
            int gr = row0 + r;
            float4 v = make_float4(0.f, 0.f, 0.f, 0.f);
            if (gr < N_NODES)
                v = *(const float4*)&Asrc[(size_t)gr * K + kc + q * 4];
            *(float4*)&As[r][q * 4] = v;
        }
        // ---- stage B chunk raw: straight float4 copy of W[k][n] ----
#pragma unroll
        for (int i = 0; i < 4; i++) {
            int idx = tid + i * 128;            // 0..511
            int k = idx >> 4, n4 = idx & 15;
            *(float4*)&Bs[k][n4 * 4] =
                *(const float4*)&W[(size_t)(kc + k) * 64 + n4 * 4];
        }
        __syncthreads();

#pragma unroll
        for (int k8 = 0; k8 < 32; k8 += 8) {
            // A fragment: 4 scalar LDS, split in-register
            float a0 = As[ar0][k8 + tg];
            float a1 = As[ar1][k8 + tg];
            float a2 = As[ar0][k8 + tg + 4];
            float a3 = As[ar1][k8 + tg + 4];
            float t0 = trunc_hi(a0), t1 = trunc_hi(a1);
            float t2 = trunc_hi(a2), t3 = trunc_hi(a3);
            uint32_t ah0 = __float_as_uint(t0), ah1 = __float_as_uint(t1);
            uint32_t ah2 = __float_as_uint(t2), ah3 = __float_as_uint(t3);
            uint32_t al0 = __float_as_uint(a0 - t0), al1 = __float_as_uint(a1 - t1);
            uint32_t al2 = __float_as_uint(a2 - t2), al3 = __float_as_uint(a3 - t3);

            // B fragments: load raw once, cache hi parts
            float br0[8], br1[8];
            uint32_t bh0[8], bh1[8];
#pragma unroll
            for (int nt = 0; nt < 8; nt++) {
                int bc = nt * 8 + g;
                br0[nt] = Bs[k8 + tg][bc];
                br1[nt] = Bs[k8 + tg + 4][bc];
                bh0[nt] = __float_as_uint(trunc_hi(br0[nt]));
                bh1[nt] = __float_as_uint(trunc_hi(br1[nt]));
            }
            // pass 1: hi*hi — 8 independent MMAs
#pragma unroll
            for (int nt = 0; nt < 8; nt++)
                mma_tf32(d[nt], ah0, ah1, ah2, ah3, bh0[nt], bh1[nt]);
            // pass 2: lo*hi
#pragma unroll
            for (int nt = 0; nt < 8; nt++)
                mma_tf32(d[nt], al0, al1, al2, al3, bh0[nt], bh1[nt]);
            // pass 3: hi*lo (lo recomputed: FADD each)
#pragma unroll
            for (int nt = 0; nt < 8; nt++) {
                uint32_t bl0 = __float_as_uint(br0[nt] - __uint_as_float(bh0[nt]));
                uint32_t bl1 = __float_as_uint(br1[nt] - __uint_as_float(bh1[nt]));
                mma_tf32(d[nt], ah0, ah1, ah2, ah3, bl0, bl1);
            }
        }
        __syncthreads();
    }

    // ---- epilogue: D frag (m16n8): rows g/g+8, cols 2tg, 2tg+1 ----
    const int r0 = row0 + warp * 16 + g;
    const int r1 = r0 + 8;
#pragma unroll
    for (int nt = 0; nt < 8; nt++) {
        int col = nt * 8 + 2 * tg;
        if (r0 < N_NODES)
            *(float2*)&g_lin[(size_t)r0 * 64 + col] = make_float2(d[nt][0], d[nt][1]);
        if (r1 < N_NODES)
            *(float2*)&g_lin[(size_t)r1 * 64 + col] = make_float2(d[nt][2], d[nt][3]);
    }
}

// ---------------- fused aggregation: selfloop + CSR gather + bias/relu/jk ----
template <int FIRST, int LAST>
__global__ void k_gather(const float* __restrict__ b) {
    unsigned gw   = (blockIdx.x * blockDim.x + threadIdx.x) >> 5;
    unsigned lane = threadIdx.x & 31;
    if (gw >= N_NODES) return;

    const float2* __restrict__ lin2 = (const float2*)g_lin;
    float dn = g_dinv[gw];
    float2 self = lin2[gw * 32u + lane];
    float2 acc = make_float2(dn * dn * self.x, dn * dn * self.y);

    int j = g_off[gw], end = g_off[gw + 1];
    for (; j + 4 <= end; j += 4) {
        int   s0 = g_csr_src[j],     s1 = g_csr_src[j + 1];
        int   s2 = g_csr_src[j + 2], s3 = g_csr_src[j + 3];
        float w0 = g_csr_w[j],       w1 = g_csr_w[j + 1];
        float w2 = g_csr_w[j + 2],   w3 = g_csr_w[j + 3];
        float2 m0 = lin2[(unsigned)s0 * 32u + lane];
        float2 m1 = lin2[(unsigned)s1 * 32u + lane];
        float2 m2 = lin2[(unsigned)s2 * 32u + lane];
        float2 m3 = lin2[(unsigned)s3 * 32u + lane];
        acc.x = fmaf(w0, m0.x, fmaf(w1, m1.x, fmaf(w2, m2.x, fmaf(w3, m3.x, acc.x))));
        acc.y = fmaf(w0, m0.y, fmaf(w1, m1.y, fmaf(w2, m2.y, fmaf(w3, m3.y, acc.y))));
    }
    for (; j < end; j++) {
        int s = g_csr_src[j];
        float w = g_csr_w[j];
        float2 m = lin2[(unsigned)s * 32u + lane];
        acc.x = fmaf(w, m.x, acc.x);
        acc.y = fmaf(w, m.y, acc.y);
    }

    float vx = fmaxf(acc.x + b[lane * 2],     0.f);
    float vy = fmaxf(acc.y + b[lane * 2 + 1], 0.f);
    if (!LAST)
        ((float2*)g_h)[gw * 32u + lane] = make_float2(vx, vy);
    float2* jk2 = (float2*)g_jk;
    if (FIRST) {
        jk2[gw * 32u + lane] = make_float2(vx, vy);
    } else {
        float2 o = jk2[gw * 32u + lane];
        jk2[gw * 32u + lane] = make_float2(fmaxf(o.x, vx), fmaxf(o.y, vy));
    }
}

// ---------------- final: logits = jk @ fcW + fcb; log_softmax ----------------
// 256 threads; block processes 16 nodes (4 passes of 4) reusing Wf in smem.
__global__ void k_final(const float* __restrict__ fcW,
                        const float* __restrict__ fcb,
                        float* __restrict__ out) {
    __shared__ float Wf[HIDDEN * N_CLASSES];
    __shared__ float row[4][HIDDEN];
    __shared__ float logits[4][N_CLASSES];
    __shared__ float lse[4];

    for (int i = threadIdx.x; i < HIDDEN * N_CLASSES; i += 256)
        Wf[i] = fcW[i];

    const int g = threadIdx.x >> 6;
    const int f = threadIdx.x & 63;

    for (int pass = 0; pass < 4; pass++) {
        const int node = blockIdx.x * 16 + pass * 4 + g;
        __syncthreads();

        if (node < N_NODES)
            row[g][f] = g_jk[(size_t)node * HIDDEN + f];
        __syncthreads();

        if (node < N_NODES && f < N_CLASSES) {
            float acc = fcb[f];
#pragma unroll
            for (int h = 0; h < HIDDEN; h++)
                acc = fmaf(row[g][h], Wf[h * N_CLASSES + f], acc);
            logits[g][f] = acc;
        }
        __syncthreads();

        if (node < N_NODES && f == 0) {
            float m = -INFINITY;
#pragma unroll
            for (int c = 0; c < N_CLASSES; c++) m = fmaxf(m, logits[g][c]);
            float s = 0.f;
#pragma unroll
            for (int c = 0; c < N_CLASSES; c++) s += expf(logits[g][c] - m);
            lse[g] = m + logf(s);
        }
        __syncthreads();

        if (node < N_NODES && f < N_CLASSES)
            out[(size_t)node * N_CLASSES + f] = logits[g][f] - lse[g];
    }
}

// ---------------- launch ----------------
extern "C" void kernel_launch(void* const* d_in, const int* in_sizes, int n_in,
                              void* d_out, int out_size) {
    const float* x      = (const float*)d_in[0];
    const int*   edge   = (const int*)d_in[1];     // int64 lowered to int32
    const float* W0     = (const float*)d_in[2];
    const float* b0     = (const float*)d_in[3];
    const float* W_rest = (const float*)d_in[4];
    const float* b_rest = (const float*)d_in[5];
    const float* fcW    = (const float*)d_in[6];
    const float* fcb    = (const float*)d_in[7];
    float* out = (float*)d_out;

    const int* src = edge;
    const int* dst = edge + N_EDGES;

    const int EB = (N_EDGES + 255) / 256;          // 6250
    const int NB = (N_NODES + 255) / 256;
    const int GB = (N_NODES + 63) / 64;            // 1563
    const int AB = (N_NODES * 32 + 255) / 256;     // 12500 (warp per node)

    // launch index 3 gets profiled by ncu -> big GEMM stays there.
    k_deg_init <<<NB, 256>>>();                         // 0
    k_deg_count<<<EB, 256>>>(dst);                      // 1
    k_scan1    <<<SCAN_NB, 1024>>>();                   // 2 (also dinv)
    k_gemm_mma<IN_FEAT, 0><<<GB, 128>>>(x, W0);         // 3  <- profiled
    k_scan2    <<<1, 128>>>();                          // 4
    k_scan3    <<<SCAN_NB, 1024>>>();                   // 5
    k_fill     <<<EB, 256>>>(src, dst);                 // 6

    // layer 0 aggregation
    k_gather<1, 0><<<AB, 256>>>(b0);

    // layers 1..5
    for (int l = 0; l < N_LAYERS - 1; l++) {
        k_gemm_mma<HIDDEN, 1><<<GB, 128>>>(nullptr, W_rest + (size_t)l * HIDDEN * HIDDEN);
        if (l < N_LAYERS - 2)
            k_gather<0, 0><<<AB, 256>>>(b_rest + (size_t)l * HIDDEN);
        else
            k_gather<0, 1><<<AB, 256>>>(b_rest + (size_t)l * HIDDEN);
    }

    // final FC + log_softmax
    k_final<<<(N_NODES + 15) / 16, 256>>>(fcW, fcb, out);
}

// round 15
// speedup vs baseline: 1.1677x; 1.0307x over previous
#include <cuda_runtime.h>
#include <cuda_bf16.h>
#include <math.h>
#include <stdint.h>

#define N_NODES   100000
#define N_EDGES   1600000
#define IN_FEAT   512
#define HIDDEN    64
#define N_CLASSES 40
#define N_LAYERS  6

#define SCAN_NB   98   // ceil(100000/1024)

// ---------------- device scratch ----------------
__device__ float g_lin[N_NODES * HIDDEN];
__device__ float g_h  [N_NODES * HIDDEN];
__device__ float g_jk [N_NODES * HIDDEN];
__device__ float g_dinv[N_NODES];
__device__ int   g_deg [N_NODES];
__device__ int   g_off [N_NODES + 1];
__device__ int   g_cur [N_NODES];
__device__ int   g_blk [SCAN_NB];
__device__ int   g_blkpref[SCAN_NB];
__device__ int   g_csr_src[N_EDGES];
__device__ float g_csr_w  [N_EDGES];

// ---------------- degree ----------------
__global__ void k_deg_init() {
    int i = blockIdx.x * blockDim.x + threadIdx.x;
    if (i < N_NODES) g_deg[i] = 1;   // self loop
}

__global__ void k_deg_count(const int* __restrict__ dst) {
    int e = blockIdx.x * blockDim.x + threadIdx.x;
    if (e < N_EDGES) atomicAdd(&g_deg[dst[e]], 1);
}

// ---------------- scan of (deg-1) -> CSR offsets; also computes dinv ------
__global__ void k_scan1() {
    __shared__ int sh[1024];
    int i = blockIdx.x * 1024 + threadIdx.x;
    int deg = (i < N_NODES) ? g_deg[i] : 1;
    if (i < N_NODES) g_dinv[i] = rsqrtf((float)deg);
    int v = (i < N_NODES) ? (deg - 1) : 0;
    sh[threadIdx.x] = v;
    __syncthreads();
#pragma unroll
    for (int o = 1; o < 1024; o <<= 1) {
        int t = (threadIdx.x >= o) ? sh[threadIdx.x - o] : 0;
        __syncthreads();
        sh[threadIdx.x] += t;
        __syncthreads();
    }
    if (i < N_NODES) g_off[i] = sh[threadIdx.x] - v;   // exclusive, intra-block
    if (threadIdx.x == 1023) g_blk[blockIdx.x] = sh[1023];
}

__global__ void k_scan2() {
    __shared__ int sh[SCAN_NB];
    if (threadIdx.x < SCAN_NB) sh[threadIdx.x] = g_blk[threadIdx.x];
    __syncthreads();
    if (threadIdx.x == 0) {
        int run = 0;
        for (int b = 0; b < SCAN_NB; b++) { int t = sh[b]; sh[b] = run; run += t; }
        g_off[N_NODES] = N_EDGES;
    }
    __syncthreads();
    if (threadIdx.x < SCAN_NB) g_blkpref[threadIdx.x] = sh[threadIdx.x];
}

__global__ void k_scan3() {
    int i = blockIdx.x * 1024 + threadIdx.x;
    if (i < N_NODES) {
        int o = g_off[i] + g_blkpref[blockIdx.x];
        g_off[i] = o;
        g_cur[i] = o;
    }
}

__global__ void k_fill(const int* __restrict__ src, const int* __restrict__ dst) {
    int e = blockIdx.x * blockDim.x + threadIdx.x;
    if (e < N_EDGES) {
        int s = src[e], d = dst[e];
        int p = atomicAdd(&g_cur[d], 1);
        g_csr_src[p] = s;
        g_csr_w[p]   = g_dinv[s] * g_dinv[d];
    }
}

// =========== mma.sync tf32x3 GEMM: g_lin[N,64] = A[N,K] @ W[K,64] ===========
// 64x64 block tile, 128 threads (4 warps). Warp = rows warp*16..+15 x 64 cols
// (8 m16n8k8 tiles). K chunks of 32, DOUBLE-BUFFERED via cp.async so the
// global-load latency of chunk c+1 hides behind the 96 MMAs of chunk c.
// Smem raw fp32 (A pitch 36, B pitch 72 — conflict-free); hi/lo in-register.
// tf32x3: D += Ahi*Bhi + Alo*Bhi + Ahi*Blo.

__device__ __forceinline__ void mma_tf32(float d[4],
                                         uint32_t a0, uint32_t a1, uint32_t a2, uint32_t a3,
                                         uint32_t b0, uint32_t b1) {
    asm("mma.sync.aligned.m16n8k8.row.col.f32.tf32.tf32.f32 "
        "{%0,%1,%2,%3}, {%4,%5,%6,%7}, {%8,%9}, {%0,%1,%2,%3};"
        : "+f"(d[0]), "+f"(d[1]), "+f"(d[2]), "+f"(d[3])
        : "r"(a0), "r"(a1), "r"(a2), "r"(a3), "r"(b0), "r"(b1));
}

__device__ __forceinline__ float trunc_hi(float x) {
    return __uint_as_float(__float_as_uint(x) & 0xFFFFE000u);
}

__device__ __forceinline__ void cp16(void* smem, const void* gmem, int valid) {
    uint32_t s = (uint32_t)__cvta_generic_to_shared(smem);
    asm volatile("cp.async.cg.shared.global [%0], [%1], 16, %2;"
                 :: "r"(s), "l"(gmem), "r"(valid ? 16 : 0));
}
#define CP_COMMIT() asm volatile("cp.async.commit_group;" ::: "memory")
#define CP_WAIT0()  asm volatile("cp.async.wait_group 0;" ::: "memory")

template <int K, int FROM_H>
__global__ void __launch_bounds__(128)
k_gemm_mma(const float* __restrict__ A, const float* __restrict__ W) {
    __shared__ __align__(16) float As[2][64][36];   // [buf][row][k] raw fp32
    __shared__ __align__(16) float Bs[2][32][72];   // [buf][k][n]   raw fp32

    const float* __restrict__ Asrc = FROM_H ? (const float*)g_h : A;

    const int tid  = threadIdx.x;
    const int warp = tid >> 5;
    const int lane = tid & 31;
    const int g    = lane >> 2;      // group id (0..7)
    const int tg   = lane & 3;       // thread in group
    const int row0 = blockIdx.x * 64;
    constexpr int NCHUNK = K / 32;

    float d[8][4];
#pragma unroll
    for (int t = 0; t < 8; t++)
#pragma unroll
        for (int c = 0; c < 4; c++) d[t][c] = 0.f;

    const int ar0 = warp * 16 + g;
    const int ar1 = ar0 + 8;

    // stage chunk c into buffer c&1 (async)
    auto stage = [&](int c) {
        const int kc = c * 32, buf = c & 1;
#pragma unroll
        for (int i = 0; i < 4; i++) {
            int idx = tid + i * 128;            // 0..511
            int r = idx >> 3, q = idx & 7;
            int gr = row0 + r;
            int ok = gr < N_NODES;
            int gsafe = ok ? gr : 0;            // valid addr even when zfilled
            cp16(&As[buf][r][q * 4],
                 &Asrc[(size_t)gsafe * K + kc + q * 4], ok);
        }
#pragma unroll
        for (int i = 0; i < 4; i++) {
            int idx = tid + i * 128;            // 0..511
            int k = idx >> 4, n4 = idx & 15;
            cp16(&Bs[buf][k][n4 * 4],
                 &W[(size_t)(kc + k) * 64 + n4 * 4], 1);
        }
        CP_COMMIT();
    };

    stage(0);

    for (int c = 0; c < NCHUNK; c++) {
        const int buf = c & 1;
        CP_WAIT0();
        __syncthreads();                 // chunk c landed; prior reads of buf^1 done
        if (c + 1 < NCHUNK) stage(c + 1);   // overlaps the MMAs below

#pragma unroll
        for (int k8 = 0; k8 < 32; k8 += 8) {
            // A fragment: 4 scalar LDS, split in-register
            float a0 = As[buf][ar0][k8 + tg];
            float a1 = As[buf][ar1][k8 + tg];
            float a2 = As[buf][ar0][k8 + tg + 4];
            float a3 = As[buf][ar1][k8 + tg + 4];
            float t0 = trunc_hi(a0), t1 = trunc_hi(a1);
            float t2 = trunc_hi(a2), t3 = trunc_hi(a3);
            uint32_t ah0 = __float_as_uint(t0), ah1 = __float_as_uint(t1);
            uint32_t ah2 = __float_as_uint(t2), ah3 = __float_as_uint(t3);
            uint32_t al0 = __float_as_uint(a0 - t0), al1 = __float_as_uint(a1 - t1);
            uint32_t al2 = __float_as_uint(a2 - t2), al3 = __float_as_uint(a3 - t3);
#pragma unroll
            for (int nt = 0; nt < 8; nt++) {
                int bc = nt * 8 + g;
                float b0 = Bs[buf][k8 + tg][bc];
                float b1 = Bs[buf][k8 + tg + 4][bc];
                float u0 = trunc_hi(b0), u1 = trunc_hi(b1);
                uint32_t bh0 = __float_as_uint(u0), bh1 = __float_as_uint(u1);
                uint32_t bl0 = __float_as_uint(b0 - u0), bl1 = __float_as_uint(b1 - u1);
                mma_tf32(d[nt], ah0, ah1, ah2, ah3, bh0, bh1);   // hi*hi
                mma_tf32(d[nt], al0, al1, al2, al3, bh0, bh1);   // lo*hi
                mma_tf32(d[nt], ah0, ah1, ah2, ah3, bl0, bl1);   // hi*lo
            }
        }
    }

    // ---- epilogue: D frag (m16n8): rows g/g+8, cols 2tg, 2tg+1 ----
    const int r0 = row0 + warp * 16 + g;
    const int r1 = r0 + 8;
#pragma unroll
    for (int nt = 0; nt < 8; nt++) {
        int col = nt * 8 + 2 * tg;
        if (r0 < N_NODES)
            *(float2*)&g_lin[(size_t)r0 * 64 + col] = make_float2(d[nt][0], d[nt][1]);
        if (r1 < N_NODES)
            *(float2*)&g_lin[(size_t)r1 * 64 + col] = make_float2(d[nt][2], d[nt][3]);
    }
}

// ---------------- fused aggregation: selfloop + CSR gather + bias/relu/jk ----
template <int FIRST, int LAST>
__global__ void k_gather(const float* __restrict__ b) {
    unsigned gw   = (blockIdx.x * blockDim.x + threadIdx.x) >> 5;
    unsigned lane = threadIdx.x & 31;
    if (gw >= N_NODES) return;

    const float2* __restrict__ lin2 = (const float2*)g_lin;
    float dn = g_dinv[gw];
    float2 self = lin2[gw * 32u + lane];
    float2 acc = make_float2(dn * dn * self.x, dn * dn * self.y);

    int j = g_off[gw], end = g_off[gw + 1];
    for (; j + 4 <= end; j += 4) {
        int   s0 = g_csr_src[j],     s1 = g_csr_src[j + 1];
        int   s2 = g_csr_src[j + 2], s3 = g_csr_src[j + 3];
        float w0 = g_csr_w[j],       w1 = g_csr_w[j + 1];
        float w2 = g_csr_w[j + 2],   w3 = g_csr_w[j + 3];
        float2 m0 = lin2[(unsigned)s0 * 32u + lane];
        float2 m1 = lin2[(unsigned)s1 * 32u + lane];
        float2 m2 = lin2[(unsigned)s2 * 32u + lane];
        float2 m3 = lin2[(unsigned)s3 * 32u + lane];
        acc.x = fmaf(w0, m0.x, fmaf(w1, m1.x, fmaf(w2, m2.x, fmaf(w3, m3.x, acc.x))));
        acc.y = fmaf(w0, m0.y, fmaf(w1, m1.y, fmaf(w2, m2.y, fmaf(w3, m3.y, acc.y))));
    }
    for (; j < end; j++) {
        int s = g_csr_src[j];
        float w = g_csr_w[j];
        float2 m = lin2[(unsigned)s * 32u + lane];
        acc.x = fmaf(w, m.x, acc.x);
        acc.y = fmaf(w, m.y, acc.y);
    }

    float vx = fmaxf(acc.x + b[lane * 2],     0.f);
    float vy = fmaxf(acc.y + b[lane * 2 + 1], 0.f);
    if (!LAST)
        ((float2*)g_h)[gw * 32u + lane] = make_float2(vx, vy);
    float2* jk2 = (float2*)g_jk;
    if (FIRST) {
        jk2[gw * 32u + lane] = make_float2(vx, vy);
    } else {
        float2 o = jk2[gw * 32u + lane];
        jk2[gw * 32u + lane] = make_float2(fmaxf(o.x, vx), fmaxf(o.y, vy));
    }
}

// ---------------- final: logits = jk @ fcW + fcb; log_softmax ----------------
// 256 threads; block processes 16 nodes (4 passes of 4) reusing Wf in smem.
__global__ void k_final(const float* __restrict__ fcW,
                        const float* __restrict__ fcb,
                        float* __restrict__ out) {
    __shared__ float Wf[HIDDEN * N_CLASSES];
    __shared__ float row[4][HIDDEN];
    __shared__ float logits[4][N_CLASSES];
    __shared__ float lse[4];

    for (int i = threadIdx.x; i < HIDDEN * N_CLASSES; i += 256)
        Wf[i] = fcW[i];

    const int g = threadIdx.x >> 6;
    const int f = threadIdx.x & 63;

    for (int pass = 0; pass < 4; pass++) {
        const int node = blockIdx.x * 16 + pass * 4 + g;
        __syncthreads();

        if (node < N_NODES)
            row[g][f] = g_jk[(size_t)node * HIDDEN + f];
        __syncthreads();

        if (node < N_NODES && f < N_CLASSES) {
            float acc = fcb[f];
#pragma unroll
            for (int h = 0; h < HIDDEN; h++)
                acc = fmaf(row[g][h], Wf[h * N_CLASSES + f], acc);
            logits[g][f] = acc;
        }
        __syncthreads();

        if (node < N_NODES && f == 0) {
            float m = -INFINITY;
#pragma unroll
            for (int c = 0; c < N_CLASSES; c++) m = fmaxf(m, logits[g][c]);
            float s = 0.f;
#pragma unroll
            for (int c = 0; c < N_CLASSES; c++) s += expf(logits[g][c] - m);
            lse[g] = m + logf(s);
        }
        __syncthreads();

        if (node < N_NODES && f < N_CLASSES)
            out[(size_t)node * N_CLASSES + f] = logits[g][f] - lse[g];
    }
}

// ---------------- launch ----------------
extern "C" void kernel_launch(void* const* d_in, const int* in_sizes, int n_in,
                              void* d_out, int out_size) {
    const float* x      = (const float*)d_in[0];
    const int*   edge   = (const int*)d_in[1];     // int64 lowered to int32
    const float* W0     = (const float*)d_in[2];
    const float* b0     = (const float*)d_in[3];
    const float* W_rest = (const float*)d_in[4];
    const float* b_rest = (const float*)d_in[5];
    const float* fcW    = (const float*)d_in[6];
    const float* fcb    = (const float*)d_in[7];
    float* out = (float*)d_out;

    const int* src = edge;
    const int* dst = edge + N_EDGES;

    const int EB = (N_EDGES + 255) / 256;          // 6250
    const int NB = (N_NODES + 255) / 256;
    const int GB = (N_NODES + 63) / 64;            // 1563
    const int AB = (N_NODES * 32 + 255) / 256;     // 12500 (warp per node)

    // launch index 3 gets profiled by ncu -> big GEMM stays there.
    k_deg_init <<<NB, 256>>>();                         // 0
    k_deg_count<<<EB, 256>>>(dst);                      // 1
    k_scan1    <<<SCAN_NB, 1024>>>();                   // 2 (also dinv)
    k_gemm_mma<IN_FEAT, 0><<<GB, 128>>>(x, W0);         // 3  <- profiled
    k_scan2    <<<1, 128>>>();                          // 4
    k_scan3    <<<SCAN_NB, 1024>>>();                   // 5
    k_fill     <<<EB, 256>>>(src, dst);                 // 6

    // layer 0 aggregation
    k_gather<1, 0><<<AB, 256>>>(b0);

    // layers 1..5
    for (int l = 0; l < N_LAYERS - 1; l++) {
        k_gemm_mma<HIDDEN, 1><<<GB, 128>>>(nullptr, W_rest + (size_t)l * HIDDEN * HIDDEN);
        if (l < N_LAYERS - 2)
            k_gather<0, 0><<<AB, 256>>>(b_rest + (size_t)l * HIDDEN);
        else
            k_gather<0, 1><<<AB, 256>>>(b_rest + (size_t)l * HIDDEN);
    }

    // final FC + log_softmax
    k_final<<<(N_NODES + 15) / 16, 256>>>(fcW, fcb, out);
}